// round 16
// baseline (speedup 1.0000x reference)
#include <cuda_runtime.h>

// Problem constants (fixed for this registry problem instance)
#define BB 32
#define ZZ 384
#define NV 68
#define MC 46
#define DC 7
#define EE (MC*DC)          // 322
#define NG 4                // variables per final-kernel block (68 = 17*4)
#define NGRP (NV/NG)        // 17
#define MAXD 8              // unrolled predicated edge batch

// Device scratch (no cudaMalloc allowed)
__device__ float g_xaT[BB*NV*ZZ];        // transposed xa, layout [b][n][z]
// c2v as int8 = 2*value (exact half-integers in [-7.5,7.5]), VARIABLE z-domain
// rows [b][e][zv], zv=(zm+shift_e)%Z. Double-buffered: iteration it reads
// buf[(it+1)&1], writes buf[it&1] -> no intra-kernel RAW race.
__device__ signed char g_c2vA[BB*EE*ZZ];
__device__ signed char g_c2vB[BB*EE*ZZ];
__device__ int g_inv_off[NV+1];          // CSR: variable -> its edges
__device__ int g_inv_eoff[EE];           // per edge (var-sorted): e*ZZ

// ---------------------------------------------------------------------------
// Init: tiled transpose xa[b][z][n] -> g_xaT [b][n][z].
// ---------------------------------------------------------------------------
__global__ void k_init(const float* __restrict__ xa) {
    __shared__ float tile[32][33];
    int bid = blockIdx.x;
    int nt = bid % 3;                 // n-tile (0..2, covers 96 >= 68)
    int zt = (bid / 3) % (ZZ/32);     // z-tile
    int b  = bid / (3 * (ZZ/32));
    int n0 = nt * 32, z0 = zt * 32;
    int tx = threadIdx.x, ty = threadIdx.y;

    int n = n0 + tx;
#pragma unroll
    for (int r = 0; r < 4; r++) {
        int z = z0 + ty + r*8;
        if (n < NV) tile[ty + r*8][tx] = xa[(b*ZZ + z)*NV + n];
    }
    __syncthreads();
#pragma unroll
    for (int r = 0; r < 4; r++) {
        int nn = n0 + ty + r*8;
        int zz = z0 + tx;
        if (nn < NV) g_xaT[(b*NV + nn)*ZZ + zz] = tile[tx][ty + r*8];
    }
}

// ---------------------------------------------------------------------------
// Build inverse index: variable n -> list of e*ZZ.
// ---------------------------------------------------------------------------
__global__ void k_build_inv(const int* __restrict__ vn) {
    __shared__ int off[NV+1];
    __shared__ int cur[NV];
    int t = threadIdx.x;
    for (int i = t; i <= NV; i += blockDim.x) off[i] = 0;
    __syncthreads();
    for (int e = t; e < EE; e += blockDim.x) atomicAdd(&off[vn[e] + 1], 1);
    __syncthreads();
    if (t == 0) {
        int s = 0;
        for (int i = 0; i <= NV; i++) { s += off[i]; off[i] = s; }
    }
    __syncthreads();
    for (int i = t; i <= NV; i += blockDim.x) g_inv_off[i] = off[i];
    for (int i = t; i <  NV; i += blockDim.x) cur[i] = off[i];
    __syncthreads();
    for (int e = t; e < EE; e += blockDim.x) {
        int p = atomicAdd(&cur[vn[e]], 1);
        g_inv_eoff[p] = e * ZZ;
    }
}

// ---------------------------------------------------------------------------
// Per-iteration kernel: check-node min-sum with INLINE variable-node totals.
// One block per (b, check c), 384 threads = zm. For edge j:
//   zv_j = (zm + shift_j) % Z
//   S_j  = sum over ALL edges of variable n_j of old c2v bytes at column zv_j
//          (exact integer; includes own edge)
//   t_j  = fmaf(S_j, 0.5, xa[n_j][zv_j])   == fl(xa + S)  (JAX tot+llr)
//   x_j  = t_j - 0.5*oldq_j                (oldq = own old byte)
// then min-sum / quantize / sign exactly as the committed R11 kernel, writing
// int8 c2v to the WRITE buffer. Reads only the READ buffer -> race-free.
// ---------------------------------------------------------------------------
__global__ void __launch_bounds__(ZZ) k_iter(
    const int* __restrict__ vn, const int* __restrict__ sh,
    const float* __restrict__ cw, int it, int first, int wpar) {
    int c = blockIdx.x % MC;
    int b = blockIdx.x / MC;
    int zm = threadIdx.x;

    __shared__ int s_n[DC], s_s[DC], s_deg[DC];
    __shared__ int s_eo[DC][16];
    if (threadIdx.x < DC) {
        int e = c * DC + threadIdx.x;
        s_n[threadIdx.x] = vn[e];
        s_s[threadIdx.x] = sh[e];
    }
    __syncthreads();
    if (threadIdx.x < DC*16) {
        int j = threadIdx.x / 16, k = threadIdx.x % 16;
        int n = s_n[j];
        int k0 = g_inv_off[n], k1 = g_inv_off[n+1];
        if (k == 0) s_deg[j] = k1 - k0;
        if (k < k1 - k0) s_eo[j][k] = g_inv_eoff[k0 + k];
    }
    __syncthreads();

    const signed char* cvr = (wpar ? g_c2vA : g_c2vB) + b*EE*ZZ;  // read: other buf
    signed char*       cvw = (wpar ? g_c2vB : g_c2vA) + b*EE*ZZ;  // write buf
    const float* xab = g_xaT + b*NV*ZZ;
    float w = __ldg(cw + it);

    int zv[DC];
#pragma unroll
    for (int j = 0; j < DC; j++) {
        int t2 = zm + s_s[j]; if (t2 >= ZZ) t2 -= ZZ;
        zv[j] = t2;
    }

    // independent loads first: xa gathers + own old bytes
    float xv[DC];
#pragma unroll
    for (int j = 0; j < DC; j++) xv[j] = xab[s_n[j]*ZZ + zv[j]];
    int oldq[DC];
#pragma unroll
    for (int j = 0; j < DC; j++)
        oldq[j] = first ? 0 : (int)cvr[(c*DC + j)*ZZ + zv[j]];

    // inline variable totals: S_j = sum of old c2v bytes over edges(n_j)
    int S[DC];
#pragma unroll
    for (int j = 0; j < DC; j++) S[j] = 0;
    if (!first) {
#pragma unroll
        for (int j = 0; j < DC; j++) {
            int deg = s_deg[j];
            int acc = 0;
#pragma unroll
            for (int k = 0; k < MAXD; k++) {
                int q = (k < deg) ? (int)cvr[s_eo[j][k] + zv[j]] : 0;
                acc += q;
            }
            for (int k = MAXD; k < deg; k++)            // rare high degree
                acc += (int)cvr[s_eo[j][k] + zv[j]];
            S[j] = acc;
        }
    }

    float mn1 = 1e30f, mn2 = 1e30f;
    int arg = 0;
    unsigned sb = 0;
#pragma unroll
    for (int j = 0; j < DC; j++) {
        float t = fmaf((float)S[j], 0.5f, xv[j]);       // fl(xa + S), exact S
        float x = t - (float)oldq[j] * 0.5f;            // minus own old c2v
        x = fminf(fmaxf(x, -20.0f), 20.0f);
        if (x < 0.0f) sb |= (1u << j);
        float a = fabsf(x);
        if (a < mn1) { mn2 = mn1; mn1 = a; arg = j; }
        else         { mn2 = fminf(mn2, a); }
    }
    int par = __popc(sb) & 1;
    // quantize: clip(round(2*w*min), +-15); rintf = round-half-even = jnp.round
    int iq1 = (int)fminf(fmaxf(rintf(2.0f * (w * mn1)), -15.0f), 15.0f);
    int iq2 = (int)fminf(fmaxf(rintf(2.0f * (w * mn2)), -15.0f), 15.0f);

#pragma unroll
    for (int j = 0; j < DC; j++) {
        int q = (j == arg) ? iq2 : iq1;                 // branch-free SEL
        int neg = (par ^ (int)(sb >> j)) & 1;           // extrinsic sign
        cvw[(c*DC + j)*ZZ + zv[j]] = (signed char)(neg ? -q : q);
    }
}

// ---------------------------------------------------------------------------
// Final output: out[b][n][z] = fl(xa + 0.5*S) from the last-written buffer.
// R12-measured shape: one block per (b, NG=4 vars), 384 threads, predicated
// batch loads, 4 z's per thread (one LDG.32 of 4 bytes per edge). Bit-exact.
// ---------------------------------------------------------------------------
__global__ void __launch_bounds__(ZZ) k_final(int rpar, float* __restrict__ dst) {
    int n0 = (blockIdx.x % NGRP) * NG;
    int b  = blockIdx.x / NGRP;
    int nn = threadIdx.x / (ZZ/4);           // 0..3, uniform per warp
    int z4 = (threadIdx.x % (ZZ/4)) * 4;

    __shared__ int s_eo[NG][16];
    __shared__ int s_k0[NG+1];
    if (threadIdx.x <= NG) s_k0[threadIdx.x] = g_inv_off[n0 + threadIdx.x];
    __syncthreads();
    int base = s_k0[0];
    int tot_e = s_k0[NG] - base;
    if (threadIdx.x < tot_e) {
        int eo = g_inv_eoff[base + threadIdx.x];
        int i = threadIdx.x + base;
        int g = 0;
        while (i >= s_k0[g+1]) g++;
        s_eo[g][i - s_k0[g]] = eo;
    }
    __syncthreads();

    int deg = s_k0[nn+1] - s_k0[nn];
    const signed char* cvb = (rpar ? g_c2vB : g_c2vA) + b*EE*ZZ + z4;

    int eo[MAXD];
#pragma unroll
    for (int k = 0; k < MAXD; k++) eo[k] = s_eo[nn][k];
    int v[MAXD];
#pragma unroll
    for (int k = 0; k < MAXD; k++)
        v[k] = (k < deg) ? *(const int*)(cvb + eo[k]) : 0;

    int a0 = 0, a1 = 0, a2 = 0, a3 = 0;
#pragma unroll
    for (int k = 0; k < MAXD; k++) {
        a0 += (v[k] << 24) >> 24;
        a1 += (v[k] << 16) >> 24;
        a2 += (v[k] <<  8) >> 24;
        a3 +=  v[k]        >> 24;
    }
    for (int k = MAXD; k < deg; k++) {
        int vv = *(const int*)(cvb + s_eo[nn][k]);
        a0 += (vv << 24) >> 24;
        a1 += (vv << 16) >> 24;
        a2 += (vv <<  8) >> 24;
        a3 +=  vv        >> 24;
    }

    int idx = (b*NV + n0 + nn)*ZZ + z4;
    float4 xa4 = __ldg((const float4*)(g_xaT + idx));
    float4 o;
    o.x = fmaf((float)a0, 0.5f, xa4.x);      // sum*0.5 exact; one rounded add
    o.y = fmaf((float)a1, 0.5f, xa4.y);
    o.z = fmaf((float)a2, 0.5f, xa4.z);
    o.w = fmaf((float)a3, 0.5f, xa4.w);
    *(float4*)(dst + idx) = o;               // out[b, n*Z + z] == [b][n][z]
}

// ---------------------------------------------------------------------------
extern "C" void kernel_launch(void* const* d_in, const int* in_sizes, int n_in,
                              void* d_out, int out_size) {
    const float* xa = (const float*)d_in[0];
    const float* cw = (const float*)d_in[1];
    const int*   vn = (const int*)d_in[2];
    // d_in[3] = cn_idx: structure is repeat(arange(M), dc) -> implicit (e/7)
    const int*   sh = (const int*)d_in[4];

    int iters = in_sizes[1];   // cn_weights length = 8

    k_init<<<BB * (ZZ/32) * 3, dim3(32, 8)>>>(xa);
    k_build_inv<<<1, 256>>>(vn);

    for (int it = 0; it < iters; ++it)
        k_iter<<<BB*MC, ZZ>>>(vn, sh, cw, it, it == 0, it & 1);

    k_final<<<BB*NGRP, ZZ>>>((iters-1) & 1, (float*)d_out);
}

// round 17
// speedup vs baseline: 1.7661x; 1.7661x over previous
#include <cuda_runtime.h>

// Problem constants (fixed for this registry problem instance)
#define BB 32
#define ZZ 384
#define NV 68
#define MC 46
#define DC 7
#define EE (MC*DC)          // 322
#define TOTF (BB*NV*ZZ)     // 835,584 floats

// Device scratch (no cudaMalloc allowed)
__device__ float g_xaT[TOTF];            // transposed xa, layout [b][n][z]
// Variable-node accumulators: acc[p][b][n][z] = sum of c2v messages (exact
// half-integer float sums -> atomicAdd order-independent). Double-buffered.
__device__ float g_accA[TOTF];
__device__ float g_accB[TOTF];
// c2v as int8 = 2*value, check-row layout [b][c*DC+j][zv] (VARIABLE z-domain).
// Each byte is read+written only by the same thread (same b,c,zm) -> 1 buffer.
__device__ signed char g_c2v8[BB*EE*ZZ];

// ---------------------------------------------------------------------------
// Init: tiled transpose xa[b][z][n] -> g_xaT [b][n][z]; zero acc buffer A
// (read buffer of iteration 0).
// ---------------------------------------------------------------------------
__global__ void k_init(const float* __restrict__ xa) {
    __shared__ float tile[32][33];
    int bid = blockIdx.x;
    int nt = bid % 3;                 // n-tile (0..2, covers 96 >= 68)
    int zt = (bid / 3) % (ZZ/32);     // z-tile
    int b  = bid / (3 * (ZZ/32));
    int n0 = nt * 32, z0 = zt * 32;
    int tx = threadIdx.x, ty = threadIdx.y;

    int n = n0 + tx;
#pragma unroll
    for (int r = 0; r < 4; r++) {
        int z = z0 + ty + r*8;
        if (n < NV) tile[ty + r*8][tx] = xa[(b*ZZ + z)*NV + n];
    }
    __syncthreads();
#pragma unroll
    for (int r = 0; r < 4; r++) {
        int nn = n0 + ty + r*8;
        int zz = z0 + tx;
        if (nn < NV) g_xaT[(b*NV + nn)*ZZ + zz] = tile[tx][ty + r*8];
    }
}

// ---------------------------------------------------------------------------
// Zero one acc buffer (float4 grid-stride).
// ---------------------------------------------------------------------------
__global__ void k_zero(int which) {
    float4* p = (float4*)(which ? g_accB : g_accA);
    int i = blockIdx.x * blockDim.x + threadIdx.x;
    int stride = gridDim.x * blockDim.x;
    for (; i < TOTF/4; i += stride)
        p[i] = make_float4(0.f, 0.f, 0.f, 0.f);
}

// ---------------------------------------------------------------------------
// Per-iteration kernel: check-node min-sum + scatter-add of new messages.
// One block per (b, check c), 384 threads = zm. Edge j, zv_j=(zm+shift_j)%Z:
//   t_j = fl(xa[n_j,zv_j] + acc_cur[n_j,zv_j])   (acc = exact tot, JAX order)
//   x_j = fl(t_j - 0.5*oldq_j); clip; min-sum; quantize (rintf = half-even);
//   write int8 c2v; atomicAdd(+-q/2) into acc_next (exact half-integer sums).
// ---------------------------------------------------------------------------
__global__ void __launch_bounds__(ZZ) k_phase2(
    const int* __restrict__ vn, const int* __restrict__ sh,
    const float* __restrict__ cw, int it, int first, int wpar) {
    int c = blockIdx.x % MC;
    int b = blockIdx.x / MC;
    int zm = threadIdx.x;

    __shared__ int s_n[DC], s_s[DC];
    if (threadIdx.x < DC) {
        int e = c * DC + threadIdx.x;
        s_n[threadIdx.x] = vn[e];
        s_s[threadIdx.x] = sh[e];
    }
    __syncthreads();

    const float* xab  = g_xaT + b*NV*ZZ;
    const float* accr = (wpar ? g_accA : g_accB) + b*NV*ZZ;  // read buffer
    float*       accw = (wpar ? g_accB : g_accA) + b*NV*ZZ;  // scatter target
    signed char* cvb  = g_c2v8 + (b*EE + c*DC)*ZZ;           // own rows
    float w = __ldg(cw + it);

    int zv[DC], ga[DC];
#pragma unroll
    for (int j = 0; j < DC; j++) {
        int t2 = zm + s_s[j]; if (t2 >= ZZ) t2 -= ZZ;
        zv[j] = t2;
        ga[j] = s_n[j]*ZZ + t2;          // gather/scatter address (floats)
    }

    // independent loads first (MLP): xa + acc gathers, own old bytes
    float xv[DC], av[DC];
    int oldq[DC];
#pragma unroll
    for (int j = 0; j < DC; j++) xv[j] = xab[ga[j]];
#pragma unroll
    for (int j = 0; j < DC; j++) av[j] = first ? 0.0f : accr[ga[j]];
#pragma unroll
    for (int j = 0; j < DC; j++) oldq[j] = first ? 0 : (int)cvb[j*ZZ + zv[j]];

    float mn1 = 1e30f, mn2 = 1e30f;
    int arg = 0;
    unsigned sb = 0;
#pragma unroll
    for (int j = 0; j < DC; j++) {
        float t = xv[j] + av[j];                  // fl(xa + tot), tot exact
        float x = t - (float)oldq[j] * 0.5f;      // minus own old c2v (exact)
        x = fminf(fmaxf(x, -20.0f), 20.0f);
        if (x < 0.0f) sb |= (1u << j);
        float a = fabsf(x);
        if (a < mn1) { mn2 = mn1; mn1 = a; arg = j; }
        else         { mn2 = fminf(mn2, a); }
    }
    int par = __popc(sb) & 1;
    // quantize: clip(round(2*w*min), +-15); rintf = round-half-even = jnp.round
    int iq1 = (int)fminf(fmaxf(rintf(2.0f * (w * mn1)), -15.0f), 15.0f);
    int iq2 = (int)fminf(fmaxf(rintf(2.0f * (w * mn2)), -15.0f), 15.0f);

#pragma unroll
    for (int j = 0; j < DC; j++) {
        int q = (j == arg) ? iq2 : iq1;           // branch-free SEL
        int neg = (par ^ (int)(sb >> j)) & 1;     // extrinsic sign
        int sq = neg ? -q : q;
        cvb[j*ZZ + zv[j]] = (signed char)sq;      // int8 message (own byte)
        // scatter-add exact half-integer message into next-iteration acc
        atomicAdd(accw + ga[j], (float)sq * 0.5f);
    }
}

// ---------------------------------------------------------------------------
// Final output: out[b][n][z] = fl(xa + acc) elementwise (acc = exact tot).
// ---------------------------------------------------------------------------
__global__ void k_final(int rpar, float* __restrict__ dst) {
    const float4* xa4 = (const float4*)g_xaT;
    const float4* ac4 = (const float4*)(rpar ? g_accB : g_accA);
    float4* o4 = (float4*)dst;
    int i = blockIdx.x * blockDim.x + threadIdx.x;
    int stride = gridDim.x * blockDim.x;
    for (; i < TOTF/4; i += stride) {
        float4 x = xa4[i], a = ac4[i];
        o4[i] = make_float4(x.x + a.x, x.y + a.y, x.z + a.z, x.w + a.w);
    }
}

// ---------------------------------------------------------------------------
extern "C" void kernel_launch(void* const* d_in, const int* in_sizes, int n_in,
                              void* d_out, int out_size) {
    const float* xa = (const float*)d_in[0];
    const float* cw = (const float*)d_in[1];
    const int*   vn = (const int*)d_in[2];
    // d_in[3] = cn_idx: structure is repeat(arange(M), dc) -> implicit (e/7)
    const int*   sh = (const int*)d_in[4];

    int iters = in_sizes[1];   // cn_weights length = 8

    k_init<<<BB * (ZZ/32) * 3, dim3(32, 8)>>>(xa);

    // iteration it: reads acc[it&1 ? B : A]... defined via wpar = it&1:
    //   wpar=0 -> read B, write A;  wpar=1 -> read A, write B.
    // it=0 must READ a zeroed buffer: wpar(0)=0 reads B -> zero B first.
    k_zero<<<512, 256>>>(1);
    for (int it = 0; it < iters; ++it) {
        int wpar = it & 1;                       // write A (0) / B (1)
        k_zero<<<512, 256>>>(wpar ? 1 : 0);      // clear scatter target
        k_phase2<<<BB*MC, ZZ>>>(vn, sh, cw, it, it == 0, wpar);
    }
    // last write buffer: wpar(iters-1)=1 -> B when iters even
    k_final<<<512, 256>>>(((iters-1) & 1) ? 1 : 0, (float*)d_out);
}